// round 11
// baseline (speedup 1.0000x reference)
#include <cuda_runtime.h>

#define B_  2
#define DD  64
#define HH  256
#define WW  256
#define HW  (HH*WW)
#define DHW (DD*HW)
#define PD  (DD+2)
#define PH  (HH+2)
#define PW  (WW+2)
#define PHW (PH*PW)      // 66564

// Zero-padded moving channel (channel 0), per batch. 35.1 MB.
__device__ float g_xpad[B_ * PD * PHW];
// Weights repacked for cheap broadcast: pair = (w_oc0, w_oc1), solo = w_oc2.
// Index = (kz*9 + ky*3 + kx) * 2 + c.
__device__ float2 g_wpair[54];
__device__ float  g_wsolo[54];
__device__ float  g_bias[3];

// ---------------------------------------------------------------------------
// Kernel 1: padded moving image. Grid (PH, PD, B_), 288 threads cover the
// 258-wide row in one step. Block (0,0,0) also repacks the weights (this
// kernel always precedes reg3d on the stream).
// ---------------------------------------------------------------------------
__global__ void __launch_bounds__(288) pad_kernel(const float* __restrict__ x,
                                                  const float* __restrict__ wp,
                                                  const float* __restrict__ bp) {
    const int y = blockIdx.x;
    const int z = blockIdx.y;
    const int b = blockIdx.z;

    if (y == 0 && z == 0 && b == 0) {
        int i = threadIdx.x;          // i = (kz*9+ky*3+kx)*2 + c
        if (i < 54) {
            int c  = i & 1;
            int k  = i >> 1;
            int wo = c * 27 + k;
            g_wpair[i] = make_float2(wp[wo], wp[54 + wo]);
            g_wsolo[i] = wp[108 + wo];
        }
        if (i < 3) g_bias[i] = bp[i];
    }

    const int col = threadIdx.x;
    if (col >= PW) return;
    const bool zyok = ((unsigned)(z - 1) < (unsigned)DD) &&
                      ((unsigned)(y - 1) < (unsigned)HH);
    float v = 0.f;
    const int gx = col - 1;
    if (zyok && (unsigned)gx < (unsigned)WW) {
        v = __ldg(x + (size_t)b * 2 * DHW + (size_t)(z - 1) * HW + (y - 1) * WW + gx);
    }
    g_xpad[(size_t)b * PD * PHW + (size_t)z * PHW + y * PW + col] = v;
}

// ---------------------------------------------------------------------------
// Kernel 2: fused offset-conv + trilinear deformable sampling + fixed copy.
// Byte-identical structure to the 200us R5 kernel (lane = x, 4 consecutive
// y per thread, direct 3-LDG x-halo, FMA order kz->ky->kx->c with exact-zero
// OOB taps -> bit-identical results). Two deltas vs R5:
//   - weights fetched as LDS.64 pair + LDS.32 scalar (108 wf vs 162)
//   - output stores use streaming policy (__stcs), keeping L2 for inputs.
// ---------------------------------------------------------------------------
__global__ void __launch_bounds__(256) reg3d_kernel(
    const float* __restrict__ x,
    float* __restrict__ out)        // [2, 2, 64, 256, 256]
{
    __shared__ float2 swp[54];
    __shared__ float  sws[54];
    __shared__ float  sb[3];

    const int t = threadIdx.x;             // xi = t (0..255)
    const int blk = blockIdx.x;            // 8192 = 64(yq) * 64(z) * 2(b)
    const int yq = blk & 63;
    const int z  = (blk >> 6) & 63;
    const int b  = blk >> 12;
    const int y0 = yq << 2;

    if (t < 54) { swp[t] = g_wpair[t]; sws[t] = g_wsolo[t]; }
    if (t < 3)  sb[t] = g_bias[t];
    __syncthreads();

    const int xi = t;
    const float* xb = x + (size_t)b * 2 * DHW;

    bool pz[3], py[6];
    #pragma unroll
    for (int kz = 0; kz < 3; kz++) pz[kz] = (unsigned)(z + kz - 1) < (unsigned)DD;
    #pragma unroll
    for (int dy = 0; dy < 6; dy++) py[dy] = (unsigned)(y0 + dy - 1) < (unsigned)HH;
    const bool pxm = (xi >= 1), pxp = (xi < 255);

    const float* base = xb + (ptrdiff_t)(z - 1) * HW + (ptrdiff_t)(y0 - 1) * WW + xi;

    // ---- conv: 3 out channels x 4 y, FMA kz->ky->kx->c ----
    float a0[4], a1[4], a2[4];
    #pragma unroll
    for (int j = 0; j < 4; j++) { a0[j] = 0.f; a1[j] = 0.f; a2[j] = 0.f; }

    #pragma unroll
    for (int kz = 0; kz < 3; kz++) {
        float vals[2][6][3];   // [c][dy][dx], dx 0/1/2 = x-1/x/x+1
        #pragma unroll
        for (int c = 0; c < 2; c++)
            #pragma unroll
            for (int dy = 0; dy < 6; dy++) {
                const bool rowok = pz[kz] && py[dy];
                const float* p = base + (ptrdiff_t)c * DHW + (ptrdiff_t)kz * HW
                                      + (ptrdiff_t)dy * WW;
                vals[c][dy][0] = (rowok && pxm) ? __ldg(p - 1) : 0.f;
                vals[c][dy][1] = rowok          ? __ldg(p)     : 0.f;
                vals[c][dy][2] = (rowok && pxp) ? __ldg(p + 1) : 0.f;
            }

        #pragma unroll
        for (int ky = 0; ky < 3; ky++)
            #pragma unroll
            for (int kx = 0; kx < 3; kx++)
                #pragma unroll
                for (int c = 0; c < 2; c++) {
                    const int wo = (kz * 9 + ky * 3 + kx) * 2 + c;
                    const float2 w01 = swp[wo];
                    const float  w2  = sws[wo];
                    #pragma unroll
                    for (int j = 0; j < 4; j++) {
                        const float v = vals[c][j + ky][kx];
                        a0[j] = __fmaf_rn(v, w01.x, a0[j]);
                        a1[j] = __fmaf_rn(v, w01.y, a1[j]);
                        a2[j] = __fmaf_rn(v, w2,    a2[j]);
                    }
                }
    }

    // ---- sampling (op-for-op faithful) ----
    const float* xpad = g_xpad + (size_t)b * PD * PHW;
    const size_t rowbase = (size_t)b * 2 * DHW + (size_t)z * HW;
    const float b0 = sb[0], b1 = sb[1], b2 = sb[2];

    #pragma unroll
    for (int j = 0; j < 4; j++) {
        const int y = y0 + j;
        float oz = __fadd_rn(a0[j], b0);
        float oy = __fadd_rn(a1[j], b1);
        float ox = __fadd_rn(a2[j], b2);

        float qz = fminf(fmaxf(__fadd_rn((float)(z + 1), oz), 0.f), 64.f);
        float qy = fminf(fmaxf(__fadd_rn((float)(y + 1), oy), 0.f), 256.f);
        float qx = fminf(fmaxf(__fadd_rn((float)(xi + 1), ox), 0.f), 256.f);

        float lz = __fadd_rn(qz, -floorf(qz));
        float ly = __fadd_rn(qy, -floorf(qy));
        float lx = __fadd_rn(qx, -floorf(qx));
        float wz0 = __fadd_rn(1.f, -lz);
        float wy0 = __fadd_rn(1.f, -ly);
        float wx0 = __fadd_rn(1.f, -lx);

        float acc = 0.f;
        #pragma unroll
        for (int dz = 0; dz < 2; dz++) {
            float cz = __fadd_rn(qz, (float)dz);
            float wz = dz ? lz : wz0;
            float czp = __fmul_rn(cz, (float)PHW);
            #pragma unroll
            for (int dy = 0; dy < 2; dy++) {
                float cy  = __fadd_rn(qy, (float)dy);
                float wzy = __fmul_rn(wz, dy ? ly : wy0);
                float czyp = __fadd_rn(czp, __fmul_rn(cy, (float)PW));
                #pragma unroll
                for (int dx = 0; dx < 2; dx++) {
                    float cx   = __fadd_rn(qx, (float)dx);
                    float comb = __fadd_rn(czyp, cx);
                    unsigned idx = (unsigned)comb;   // trunc (astype int32)
                    float wv = __fmul_rn(wzy, dx ? lx : wx0);
                    acc = __fadd_rn(acc, __fmul_rn(__ldg(xpad + idx), wv));
                }
            }
        }

        const size_t o0 = rowbase + (size_t)y * WW + xi;
        __stcs(out + o0, acc);                                            // deformed
        __stcs(out + o0 + DHW,
               __ldg(xb + DHW + (size_t)z * HW + (size_t)y * WW + xi));   // fixed
    }
}

// ---------------------------------------------------------------------------
extern "C" void kernel_launch(void* const* d_in, const int* in_sizes, int n_in,
                              void* d_out, int out_size) {
    const float* x  = (const float*)d_in[0];
    const float* wp = (const float*)d_in[1];
    const float* bp = (const float*)d_in[2];
    float* out = (float*)d_out;

    dim3 pgrid(PH, PD, B_);
    pad_kernel<<<pgrid, 288>>>(x, wp, bp);

    // 2(b) * 64(z) * 64(y-quads) = 8192 blocks, 256 threads = full x row
    reg3d_kernel<<<8192, 256>>>(x, out);
}

// round 12
// speedup vs baseline: 1.1239x; 1.1239x over previous
#include <cuda_runtime.h>

#define B_  2
#define DD  64
#define HH  256
#define WW  256
#define HW  (HH*WW)
#define DHW (DD*HW)
#define PD  (DD+2)
#define PH  (HH+2)
#define PW  (PW_)
#define PW_ (WW+2)
#define PHW (PH*PW_)      // 66564

// Zero-padded moving channel (channel 0), per batch. 35.1 MB.
__device__ float g_xpad[B_ * PD * PHW];

// Conv weights/bias in constant memory (filled by async D2D copy at launch).
__constant__ float cw[162];
__constant__ float cb[3];

// ---------------------------------------------------------------------------
// Kernel 1: padded moving image. Grid (PH, PD, B_), 288 threads cover the
// 258-wide row in one step. Coalesced, no division.
// ---------------------------------------------------------------------------
__global__ void __launch_bounds__(288) pad_kernel(const float* __restrict__ x) {
    const int y = blockIdx.x;
    const int z = blockIdx.y;
    const int b = blockIdx.z;
    const int col = threadIdx.x;
    if (col >= PW_) return;
    const bool zyok = ((unsigned)(z - 1) < (unsigned)DD) &&
                      ((unsigned)(y - 1) < (unsigned)HH);
    float v = 0.f;
    const int gx = col - 1;
    if (zyok && (unsigned)gx < (unsigned)WW) {
        v = __ldg(x + (size_t)b * 2 * DHW + (size_t)(z - 1) * HW + (y - 1) * WW + gx);
    }
    g_xpad[(size_t)b * PD * PHW + (size_t)z * PHW + y * PW_ + col] = v;
}

// ---------------------------------------------------------------------------
// Kernel 2: fused offset-conv + trilinear deformable sampling + fixed copy.
// Structure identical to the 200us R5 kernel (lane = x, 4 consecutive y per
// thread, direct 3-LDG x-halo, FMA order kz->ky->kx->c with exact-zero OOB
// taps -> bit-identical results). Deltas vs R5:
//   - weights/bias from __constant__ (uniform-port loads, off L1tex; no smem,
//     no __syncthreads)
//   - output stores use streaming policy (__stcs).
// ---------------------------------------------------------------------------
__global__ void __launch_bounds__(256) reg3d_kernel(
    const float* __restrict__ x,
    float* __restrict__ out)        // [2, 2, 64, 256, 256]
{
    const int t = threadIdx.x;             // xi = t (0..255)
    const int blk = blockIdx.x;            // 8192 = 64(yq) * 64(z) * 2(b)
    const int yq = blk & 63;
    const int z  = (blk >> 6) & 63;
    const int b  = blk >> 12;
    const int y0 = yq << 2;

    const int xi = t;
    const float* xb = x + (size_t)b * 2 * DHW;

    bool pz[3], py[6];
    #pragma unroll
    for (int kz = 0; kz < 3; kz++) pz[kz] = (unsigned)(z + kz - 1) < (unsigned)DD;
    #pragma unroll
    for (int dy = 0; dy < 6; dy++) py[dy] = (unsigned)(y0 + dy - 1) < (unsigned)HH;
    const bool pxm = (xi >= 1), pxp = (xi < 255);

    const float* base = xb + (ptrdiff_t)(z - 1) * HW + (ptrdiff_t)(y0 - 1) * WW + xi;

    // ---- conv: 3 out channels x 4 y, FMA kz->ky->kx->c ----
    float a0[4], a1[4], a2[4];
    #pragma unroll
    for (int j = 0; j < 4; j++) { a0[j] = 0.f; a1[j] = 0.f; a2[j] = 0.f; }

    #pragma unroll
    for (int kz = 0; kz < 3; kz++) {
        float vals[2][6][3];   // [c][dy][dx], dx 0/1/2 = x-1/x/x+1
        #pragma unroll
        for (int c = 0; c < 2; c++)
            #pragma unroll
            for (int dy = 0; dy < 6; dy++) {
                const bool rowok = pz[kz] && py[dy];
                const float* p = base + (ptrdiff_t)c * DHW + (ptrdiff_t)kz * HW
                                      + (ptrdiff_t)dy * WW;
                vals[c][dy][0] = (rowok && pxm) ? __ldg(p - 1) : 0.f;
                vals[c][dy][1] = rowok          ? __ldg(p)     : 0.f;
                vals[c][dy][2] = (rowok && pxp) ? __ldg(p + 1) : 0.f;
            }

        #pragma unroll
        for (int ky = 0; ky < 3; ky++)
            #pragma unroll
            for (int kx = 0; kx < 3; kx++)
                #pragma unroll
                for (int c = 0; c < 2; c++) {
                    const int wo = c * 27 + kz * 9 + ky * 3 + kx;
                    const float w0 = cw[wo];
                    const float w1 = cw[54 + wo];
                    const float w2 = cw[108 + wo];
                    #pragma unroll
                    for (int j = 0; j < 4; j++) {
                        const float v = vals[c][j + ky][kx];
                        a0[j] = __fmaf_rn(v, w0, a0[j]);
                        a1[j] = __fmaf_rn(v, w1, a1[j]);
                        a2[j] = __fmaf_rn(v, w2, a2[j]);
                    }
                }
    }

    // ---- sampling (op-for-op faithful) ----
    const float* xpad = g_xpad + (size_t)b * PD * PHW;
    const size_t rowbase = (size_t)b * 2 * DHW + (size_t)z * HW;
    const float b0 = cb[0], b1 = cb[1], b2 = cb[2];

    #pragma unroll
    for (int j = 0; j < 4; j++) {
        const int y = y0 + j;
        float oz = __fadd_rn(a0[j], b0);
        float oy = __fadd_rn(a1[j], b1);
        float ox = __fadd_rn(a2[j], b2);

        float qz = fminf(fmaxf(__fadd_rn((float)(z + 1), oz), 0.f), 64.f);
        float qy = fminf(fmaxf(__fadd_rn((float)(y + 1), oy), 0.f), 256.f);
        float qx = fminf(fmaxf(__fadd_rn((float)(xi + 1), ox), 0.f), 256.f);

        float lz = __fadd_rn(qz, -floorf(qz));
        float ly = __fadd_rn(qy, -floorf(qy));
        float lx = __fadd_rn(qx, -floorf(qx));
        float wz0 = __fadd_rn(1.f, -lz);
        float wy0 = __fadd_rn(1.f, -ly);
        float wx0 = __fadd_rn(1.f, -lx);

        float acc = 0.f;
        #pragma unroll
        for (int dz = 0; dz < 2; dz++) {
            float cz = __fadd_rn(qz, (float)dz);
            float wz = dz ? lz : wz0;
            float czp = __fmul_rn(cz, (float)PHW);
            #pragma unroll
            for (int dy = 0; dy < 2; dy++) {
                float cy  = __fadd_rn(qy, (float)dy);
                float wzy = __fmul_rn(wz, dy ? ly : wy0);
                float czyp = __fadd_rn(czp, __fmul_rn(cy, (float)PW_));
                #pragma unroll
                for (int dx = 0; dx < 2; dx++) {
                    float cx   = __fadd_rn(qx, (float)dx);
                    float comb = __fadd_rn(czyp, cx);
                    unsigned idx = (unsigned)comb;   // trunc (astype int32)
                    float wv = __fmul_rn(wzy, dx ? lx : wx0);
                    acc = __fadd_rn(acc, __fmul_rn(__ldg(xpad + idx), wv));
                }
            }
        }

        const size_t o0 = rowbase + (size_t)y * WW + xi;
        __stcs(out + o0, acc);                                            // deformed
        __stcs(out + o0 + DHW,
               __ldg(xb + DHW + (size_t)z * HW + (size_t)y * WW + xi));   // fixed
    }
}

// ---------------------------------------------------------------------------
extern "C" void kernel_launch(void* const* d_in, const int* in_sizes, int n_in,
                              void* d_out, int out_size) {
    const float* x  = (const float*)d_in[0];
    const float* wp = (const float*)d_in[1];
    const float* bp = (const float*)d_in[2];
    float* out = (float*)d_out;

    // weights/bias -> constant bank (device-to-device, graph-capturable)
    cudaMemcpyToSymbolAsync(cw, wp, 162 * sizeof(float), 0, cudaMemcpyDeviceToDevice);
    cudaMemcpyToSymbolAsync(cb, bp, 3 * sizeof(float), 0, cudaMemcpyDeviceToDevice);

    dim3 pgrid(PH, PD, B_);
    pad_kernel<<<pgrid, 288>>>(x);

    // 2(b) * 64(z) * 64(y-quads) = 8192 blocks, 256 threads = full x row
    reg3d_kernel<<<8192, 256>>>(x, out);
}